// round 12
// baseline (speedup 1.0000x reference)
#include <cuda_runtime.h>
#include <cuda_bf16.h>
#include <cstdint>

// out_means[b][d] = mean[d][labels[b][d]]; out_log_vars[b][d] = log_var[d][labels[b][d]]
// B = 2097152, N_DOMAINS = 8, MAX_CONCEPTS = 64.
// d_out: [means B*8 f32][log_vars B*8 f32].
//
// R12 (final) = R9 structure — the proven best wall config:
//  - 256 samples/CTA, 8192 CTAs
//  - label load hoisted above the table-load barrier (latency overlap)
//  - per-warp 1KB TMA bulk stores after __syncwarp (no second CTA barrier)
//  - cp.async.bulk.wait_group.read 0 waited by lane 0 only; other lanes exit
// plus R11's salvaged SM-side win:
//  - ONE 32B ld.global.nc.v4.b64 label load per thread (was 2x LDG.128)
// and NO L2 cache policies (both pinning experiments regressed wall).

#define N_DOMAINS 8
#define MAX_CONCEPTS 64
#define TAB (N_DOMAINS * MAX_CONCEPTS)   // 512
#define BLK 256

// Load 8 consecutive int32 labels (32B, aligned) in one instruction.
__device__ __forceinline__ void ldg_labels8(const void* p, int4& l0, int4& l1) {
    uint64_t d0, d1, d2, d3;
    asm("ld.global.nc.v4.b64 {%0,%1,%2,%3}, [%4];"
        : "=l"(d0), "=l"(d1), "=l"(d2), "=l"(d3) : "l"(p));
    l0.x = (int)(d0);       l0.y = (int)(d0 >> 32);
    l0.z = (int)(d1);       l0.w = (int)(d1 >> 32);
    l1.x = (int)(d2);       l1.y = (int)(d2 >> 32);
    l1.z = (int)(d3);       l1.w = (int)(d3 >> 32);
}

__global__ __launch_bounds__(BLK)
void concept_gauss_kernel(const int4* __restrict__ labels4,   // [B*2]
                          const float* __restrict__ mean,     // [512]
                          const float* __restrict__ log_var,  // [512]
                          float* __restrict__ out,            // [2*B*8]
                          int B)
{
    __shared__ float s_mean[TAB];
    __shared__ float s_var[TAB];
    __shared__ alignas(128) float st_mean[BLK * N_DOMAINS];  // 8 KB, 1KB/warp
    __shared__ alignas(128) float st_var[BLK * N_DOMAINS];   // 8 KB, 1KB/warp

    const int t = threadIdx.x;
    const int w = t >> 5;
    const int lane = t & 31;

    const long base = (long)blockIdx.x * BLK;
    const long b    = base + t;
    const bool full_block = (base + BLK) <= (long)B;
    const bool live = b < (long)B;

    // ---- FIRST: one 32B label load (no deps); its DRAM latency overlaps the
    // table load + barrier below.
    int4 l0 = make_int4(0, 0, 0, 0), l1 = make_int4(0, 0, 0, 0);
    if (live) {
        ldg_labels8(&labels4[2 * b], l0, l1);
    }

    // ---- Table load (2 KB each) + the only CTA-wide barrier.
    s_mean[t]       = __ldg(&mean[t]);
    s_mean[t + 256] = __ldg(&mean[t + 256]);
    s_var[t]        = __ldg(&log_var[t]);
    s_var[t + 256]  = __ldg(&log_var[t + 256]);
    __syncthreads();

    if (full_block) {
        float4* pm = reinterpret_cast<float4*>(&st_mean[t * N_DOMAINS]);
        float4* pv = reinterpret_cast<float4*>(&st_var[t * N_DOMAINS]);

        pm[0] = make_float4(s_mean[0 * MAX_CONCEPTS + l0.x],
                            s_mean[1 * MAX_CONCEPTS + l0.y],
                            s_mean[2 * MAX_CONCEPTS + l0.z],
                            s_mean[3 * MAX_CONCEPTS + l0.w]);
        pm[1] = make_float4(s_mean[4 * MAX_CONCEPTS + l1.x],
                            s_mean[5 * MAX_CONCEPTS + l1.y],
                            s_mean[6 * MAX_CONCEPTS + l1.z],
                            s_mean[7 * MAX_CONCEPTS + l1.w]);
        pv[0] = make_float4(s_var[0 * MAX_CONCEPTS + l0.x],
                            s_var[1 * MAX_CONCEPTS + l0.y],
                            s_var[2 * MAX_CONCEPTS + l0.z],
                            s_var[3 * MAX_CONCEPTS + l0.w]);
        pv[1] = make_float4(s_var[4 * MAX_CONCEPTS + l1.x],
                            s_var[5 * MAX_CONCEPTS + l1.y],
                            s_var[6 * MAX_CONCEPTS + l1.z],
                            s_var[7 * MAX_CONCEPTS + l1.w]);

        // Warp-local completion of this warp's 1KB staging slices.
        __syncwarp();

        if (lane == 0) {
            // Order this warp's generic-proxy STS before async-proxy TMA reads.
            asm volatile("fence.proxy.async.shared::cta;" ::: "memory");

            uint32_t sm_m, sm_v;
            asm("{ .reg .u64 a; cvta.to.shared.u64 a, %1; cvt.u32.u64 %0, a; }"
                : "=r"(sm_m) : "l"(&st_mean[w * 32 * N_DOMAINS]));
            asm("{ .reg .u64 a; cvta.to.shared.u64 a, %1; cvt.u32.u64 %0, a; }"
                : "=r"(sm_v) : "l"(&st_var[w * 32 * N_DOMAINS]));

            const uint32_t bytes = 32 * N_DOMAINS * sizeof(float);  // 1024
            float* dst_m = out + (base + w * 32) * N_DOMAINS;
            float* dst_v = out + (long)B * N_DOMAINS + (base + w * 32) * N_DOMAINS;

            asm volatile(
                "cp.async.bulk.global.shared::cta.bulk_group [%0], [%1], %2;"
                :: "l"(dst_m), "r"(sm_m), "r"(bytes) : "memory");
            asm volatile(
                "cp.async.bulk.global.shared::cta.bulk_group [%0], [%1], %2;"
                :: "l"(dst_v), "r"(sm_v), "r"(bytes) : "memory");
            asm volatile("cp.async.bulk.commit_group;" ::: "memory");
            // Wait only for TMA smem READ completion; lane 0's residency keeps
            // the CTA's smem alive, other lanes exit immediately.
            asm volatile("cp.async.bulk.wait_group.read 0;" ::: "memory");
        }
    } else {
        // Tail (unused for B = 2^21): direct stores.
        if (live) {
            float4* o = reinterpret_cast<float4*>(out);
            long vb = 2L * B;  // float4 units
            o[2 * b]     = make_float4(s_mean[0 * MAX_CONCEPTS + l0.x],
                                       s_mean[1 * MAX_CONCEPTS + l0.y],
                                       s_mean[2 * MAX_CONCEPTS + l0.z],
                                       s_mean[3 * MAX_CONCEPTS + l0.w]);
            o[2 * b + 1] = make_float4(s_mean[4 * MAX_CONCEPTS + l1.x],
                                       s_mean[5 * MAX_CONCEPTS + l1.y],
                                       s_mean[6 * MAX_CONCEPTS + l1.z],
                                       s_mean[7 * MAX_CONCEPTS + l1.w]);
            o[vb + 2 * b]     = make_float4(s_var[0 * MAX_CONCEPTS + l0.x],
                                            s_var[1 * MAX_CONCEPTS + l0.y],
                                            s_var[2 * MAX_CONCEPTS + l0.z],
                                            s_var[3 * MAX_CONCEPTS + l0.w]);
            o[vb + 2 * b + 1] = make_float4(s_var[4 * MAX_CONCEPTS + l1.x],
                                            s_var[5 * MAX_CONCEPTS + l1.y],
                                            s_var[6 * MAX_CONCEPTS + l1.z],
                                            s_var[7 * MAX_CONCEPTS + l1.w]);
        }
    }
}

extern "C" void kernel_launch(void* const* d_in, const int* in_sizes, int n_in,
                              void* d_out, int out_size) {
    const int4*  labels4 = (const int4*)d_in[0];
    const float* mean    = (const float*)d_in[1];
    const float* log_var = (const float*)d_in[2];
    float* out = (float*)d_out;

    int B = in_sizes[0] / N_DOMAINS;   // 2097152
    int blocks = (B + BLK - 1) / BLK;  // 8192
    concept_gauss_kernel<<<blocks, BLK>>>(labels4, mean, log_var, out, B);
}

// round 13
// speedup vs baseline: 1.0371x; 1.0371x over previous
#include <cuda_runtime.h>
#include <cuda_bf16.h>
#include <cstdint>

// out_means[b][d] = mean[d][labels[b][d]]; out_log_vars[b][d] = log_var[d][labels[b][d]]
// B = 2097152, N_DOMAINS = 8, MAX_CONCEPTS = 64.
// d_out: [means B*8 f32][log_vars B*8 f32].
//
// FINAL (= R9, best wall config, 35.296us reproduced twice):
//  - 256 samples/CTA, 8192 CTAs
//  - 2x LDG.128 __ldcs label loads HOISTED above the table-load barrier
//    (latency overlap; the 1x v4.b64 variant deterministically regressed wall)
//  - scalar f32 smem tables (bank-conflict degree <= 2)
//  - per-warp smem staging + 1KB TMA bulk stores after __syncwarp
//    (no second CTA barrier, STG issue cost off the LSU pipe)
//  - cp.async.bulk.wait_group.read 0 (smem-read completion only) waited by
//    lane 0 per warp; all other lanes exit immediately
//  - no L2 cache policies (both pinning experiments regressed wall)

#define N_DOMAINS 8
#define MAX_CONCEPTS 64
#define TAB (N_DOMAINS * MAX_CONCEPTS)   // 512
#define BLK 256

__global__ __launch_bounds__(BLK)
void concept_gauss_kernel(const int4* __restrict__ labels4,   // [B*2]
                          const float* __restrict__ mean,     // [512]
                          const float* __restrict__ log_var,  // [512]
                          float* __restrict__ out,            // [2*B*8]
                          int B)
{
    __shared__ float s_mean[TAB];
    __shared__ float s_var[TAB];
    __shared__ alignas(128) float st_mean[BLK * N_DOMAINS];  // 8 KB, 1KB/warp
    __shared__ alignas(128) float st_var[BLK * N_DOMAINS];   // 8 KB, 1KB/warp

    const int t = threadIdx.x;
    const int w = t >> 5;
    const int lane = t & 31;

    const long base = (long)blockIdx.x * BLK;
    const long b    = base + t;
    const bool full_block = (base + BLK) <= (long)B;
    const bool live = b < (long)B;

    // ---- FIRST: issue the label loads (no dependencies) so their DRAM
    // latency overlaps the table load + barrier below.
    int4 l0 = make_int4(0, 0, 0, 0), l1 = make_int4(0, 0, 0, 0);
    if (live) {
        l0 = __ldcs(&labels4[2 * b]);
        l1 = __ldcs(&labels4[2 * b + 1]);
    }

    // ---- Table load (2 KB each) + the only CTA-wide barrier.
    s_mean[t]       = __ldg(&mean[t]);
    s_mean[t + 256] = __ldg(&mean[t + 256]);
    s_var[t]        = __ldg(&log_var[t]);
    s_var[t + 256]  = __ldg(&log_var[t + 256]);
    __syncthreads();

    if (full_block) {
        float4* pm = reinterpret_cast<float4*>(&st_mean[t * N_DOMAINS]);
        float4* pv = reinterpret_cast<float4*>(&st_var[t * N_DOMAINS]);

        pm[0] = make_float4(s_mean[0 * MAX_CONCEPTS + l0.x],
                            s_mean[1 * MAX_CONCEPTS + l0.y],
                            s_mean[2 * MAX_CONCEPTS + l0.z],
                            s_mean[3 * MAX_CONCEPTS + l0.w]);
        pm[1] = make_float4(s_mean[4 * MAX_CONCEPTS + l1.x],
                            s_mean[5 * MAX_CONCEPTS + l1.y],
                            s_mean[6 * MAX_CONCEPTS + l1.z],
                            s_mean[7 * MAX_CONCEPTS + l1.w]);
        pv[0] = make_float4(s_var[0 * MAX_CONCEPTS + l0.x],
                            s_var[1 * MAX_CONCEPTS + l0.y],
                            s_var[2 * MAX_CONCEPTS + l0.z],
                            s_var[3 * MAX_CONCEPTS + l0.w]);
        pv[1] = make_float4(s_var[4 * MAX_CONCEPTS + l1.x],
                            s_var[5 * MAX_CONCEPTS + l1.y],
                            s_var[6 * MAX_CONCEPTS + l1.z],
                            s_var[7 * MAX_CONCEPTS + l1.w]);

        // Warp-local completion of this warp's 1KB staging slices.
        __syncwarp();

        if (lane == 0) {
            // Order this warp's generic-proxy STS before async-proxy TMA reads.
            asm volatile("fence.proxy.async.shared::cta;" ::: "memory");

            uint32_t sm_m, sm_v;
            asm("{ .reg .u64 a; cvta.to.shared.u64 a, %1; cvt.u32.u64 %0, a; }"
                : "=r"(sm_m) : "l"(&st_mean[w * 32 * N_DOMAINS]));
            asm("{ .reg .u64 a; cvta.to.shared.u64 a, %1; cvt.u32.u64 %0, a; }"
                : "=r"(sm_v) : "l"(&st_var[w * 32 * N_DOMAINS]));

            const uint32_t bytes = 32 * N_DOMAINS * sizeof(float);  // 1024
            float* dst_m = out + (base + w * 32) * N_DOMAINS;
            float* dst_v = out + (long)B * N_DOMAINS + (base + w * 32) * N_DOMAINS;

            asm volatile(
                "cp.async.bulk.global.shared::cta.bulk_group [%0], [%1], %2;"
                :: "l"(dst_m), "r"(sm_m), "r"(bytes) : "memory");
            asm volatile(
                "cp.async.bulk.global.shared::cta.bulk_group [%0], [%1], %2;"
                :: "l"(dst_v), "r"(sm_v), "r"(bytes) : "memory");
            asm volatile("cp.async.bulk.commit_group;" ::: "memory");
            // Wait only for TMA smem READ completion; lane 0's residency keeps
            // the CTA's smem alive, other lanes exit immediately.
            asm volatile("cp.async.bulk.wait_group.read 0;" ::: "memory");
        }
    } else {
        // Tail (unused for B = 2^21): direct stores.
        if (live) {
            float4* o = reinterpret_cast<float4*>(out);
            long vb = 2L * B;  // float4 units
            o[2 * b]     = make_float4(s_mean[0 * MAX_CONCEPTS + l0.x],
                                       s_mean[1 * MAX_CONCEPTS + l0.y],
                                       s_mean[2 * MAX_CONCEPTS + l0.z],
                                       s_mean[3 * MAX_CONCEPTS + l0.w]);
            o[2 * b + 1] = make_float4(s_mean[4 * MAX_CONCEPTS + l1.x],
                                       s_mean[5 * MAX_CONCEPTS + l1.y],
                                       s_mean[6 * MAX_CONCEPTS + l1.z],
                                       s_mean[7 * MAX_CONCEPTS + l1.w]);
            o[vb + 2 * b]     = make_float4(s_var[0 * MAX_CONCEPTS + l0.x],
                                            s_var[1 * MAX_CONCEPTS + l0.y],
                                            s_var[2 * MAX_CONCEPTS + l0.z],
                                            s_var[3 * MAX_CONCEPTS + l0.w]);
            o[vb + 2 * b + 1] = make_float4(s_var[4 * MAX_CONCEPTS + l1.x],
                                            s_var[5 * MAX_CONCEPTS + l1.y],
                                            s_var[6 * MAX_CONCEPTS + l1.z],
                                            s_var[7 * MAX_CONCEPTS + l1.w]);
        }
    }
}

extern "C" void kernel_launch(void* const* d_in, const int* in_sizes, int n_in,
                              void* d_out, int out_size) {
    const int4*  labels4 = (const int4*)d_in[0];
    const float* mean    = (const float*)d_in[1];
    const float* log_var = (const float*)d_in[2];
    float* out = (float*)d_out;

    int B = in_sizes[0] / N_DOMAINS;   // 2097152
    int blocks = (B + BLK - 1) / BLK;  // 8192
    concept_gauss_kernel<<<blocks, BLK>>>(labels4, mean, log_var, out, B);
}